// round 12
// baseline (speedup 1.0000x reference)
#include <cuda_runtime.h>
#include <cuda_fp16.h>
#include <cstdint>
#include <math_constants.h>

#define NND 40000
#define HD  128
#define EED 640000
#define STG 4          // cp.async pipeline stages (4 rows each)

// ---------------- scratch (device globals: allocation-free) ----------------
__device__ __half   g_bufXW [(size_t)NND * HD];   // GCN GEMM out, fp16 (gathered)
__device__ __half   g_bufHH [(size_t)NND * HD];   // GAT GEMM out, fp16 (gathered)
__device__ float    g_bufACC[(size_t)NND * HD];   // relu(GCN) out, fp32 (GEMM input)
__device__ float    g_bufOUT[(size_t)NND * HD];   // GAT out, fp32 (GEMM input / pool)
__device__ int      g_deg   [NND];
__device__ float    g_dinv  [NND];
__device__ int      g_rowptr[NND];
__device__ int      g_cursor[NND];
__device__ int      g_rowtmp[NND];
__device__ int      g_bsum  [256];
__device__ int      g_boff  [256];
__device__ int      g_csrcol[EED];
__device__ uint32_t g_Bperm [HD * HD];

// ---------------- helpers ----------------
__device__ __forceinline__ float4 h8_to_f4(uint2 u) {
    __half2 a = *(__half2*)&u.x, b = *(__half2*)&u.y;
    float2 fa = __half22float2(a), fb = __half22float2(b);
    return make_float4(fa.x, fa.y, fb.x, fb.y);
}
__device__ __forceinline__ float warp_sum(float s) {
#pragma unroll
    for (int o = 16; o; o >>= 1) s += __shfl_xor_sync(0xffffffffu, s, o);
    return s;
}
__device__ __forceinline__ void cp8(uint32_t dst, const void* src) {
    asm volatile("cp.async.ca.shared.global [%0], [%1], 8;\n" :: "r"(dst), "l"(src) : "memory");
}
__device__ __forceinline__ void cp_commit() {
    asm volatile("cp.async.commit_group;\n" ::: "memory");
}
__device__ __forceinline__ void cp_wait() {
    asm volatile("cp.async.wait_group %0;\n" :: "n"(STG - 1) : "memory");
}

// ---------------- degree / norm ----------------
__global__ void k_deg_init() {
    int i = blockIdx.x * blockDim.x + threadIdx.x;
    if (i < NND) g_deg[i] = 1;
}
__global__ void k_deg_count(const int* __restrict__ row, int E) {
    int e = blockIdx.x * blockDim.x + threadIdx.x;
    if (e < E) atomicAdd(&g_deg[row[e]], 1);
}

// ---------------- hierarchical exclusive scan of (deg-1), + dinv ----------------
__global__ __launch_bounds__(256) void k_scanA() {
    __shared__ int sm[256];
    int tx = threadIdx.x;
    int i = blockIdx.x * 256 + tx;
    int d = (i < NND) ? g_deg[i] : 1;
    if (i < NND) g_dinv[i] = rsqrtf((float)d);
    int v = d - 1;
    if (i >= NND) v = 0;
    sm[tx] = v;
    __syncthreads();
#pragma unroll
    for (int off = 1; off < 256; off <<= 1) {
        int p = (tx >= off) ? sm[tx - off] : 0;
        __syncthreads();
        sm[tx] += p;
        __syncthreads();
    }
    if (i < NND) g_rowtmp[i] = sm[tx] - v;
    if (tx == 255) g_bsum[blockIdx.x] = sm[255];
}
__global__ __launch_bounds__(256) void k_scanB(int nb) {
    __shared__ int sm[256];
    int tx = threadIdx.x;
    int v = (tx < nb) ? g_bsum[tx] : 0;
    sm[tx] = v;
    __syncthreads();
#pragma unroll
    for (int off = 1; off < 256; off <<= 1) {
        int p = (tx >= off) ? sm[tx - off] : 0;
        __syncthreads();
        sm[tx] += p;
        __syncthreads();
    }
    g_boff[tx] = sm[tx] - v;
}
__global__ void k_scanC() {
    int i = blockIdx.x * blockDim.x + threadIdx.x;
    if (i < NND) {
        int rp = g_rowtmp[i] + g_boff[i >> 8];
        g_rowptr[i] = rp;
        g_cursor[i] = rp;
    }
}
__global__ void k_fill(const int* __restrict__ row, const int* __restrict__ col, int E) {
    int e = blockIdx.x * blockDim.x + threadIdx.x;
    if (e >= E) return;
    int r = row[e];
    int pos = atomicAdd(&g_cursor[r], 1);
    g_csrcol[pos] = col[e];
}

// ---------------- weight preconvert: (fold) + tf32 + fragment permute ----------------
__device__ __forceinline__ uint32_t f2tf32(float f) {
    uint32_t u;
    asm("cvt.rna.tf32.f32 %0, %1;" : "=r"(u) : "f"(f));
    return u;
}
__global__ void k_bperm(const float* __restrict__ W, int fold) {
    int t = blockIdx.x * blockDim.x + threadIdx.x;
    if (t >= HD * HD) return;
    int k = t >> 7, n = t & 127;
    float v = W[t];
    if (fold) v += W[t + HD * HD];
    int ki = k >> 3, ni = n >> 3, kk = k & 7, nn = n & 7;
    int l = (nn << 2) | (kk & 3);
    int j = kk >> 2;
    g_Bperm[(ki * 16 + ni) * 64 + l * 2 + j] = f2tf32(v);
}

// ---------------- TF32 tensor-core GEMM: Ch[M,128] = A[M,128] @ Bperm (fp16 out) ----
__device__ __forceinline__ void mma_tf32(float* d, const uint32_t* a, const uint32_t* b) {
    asm volatile(
        "mma.sync.aligned.m16n8k8.row.col.f32.tf32.tf32.f32 "
        "{%0,%1,%2,%3}, {%4,%5,%6,%7}, {%8,%9}, {%0,%1,%2,%3};"
        : "+f"(d[0]), "+f"(d[1]), "+f"(d[2]), "+f"(d[3])
        : "r"(a[0]), "r"(a[1]), "r"(a[2]), "r"(a[3]), "r"(b[0]), "r"(b[1]));
}
__global__ __launch_bounds__(256) void k_gemm_tf32(const float* __restrict__ A,
                                                   const float* __restrict__ bias,
                                                   const float* __restrict__ rowscale,
                                                   __half* __restrict__ Ch, int M) {
    __shared__ uint32_t Asp[32 * 128];
    int tid = threadIdx.x;
    int lane = tid & 31;
    int w = tid >> 5;
    int wm = w >> 2, wn = w & 3;
    int gRow0 = blockIdx.x * 128;
    float acc[4][4][4];
#pragma unroll
    for (int i = 0; i < 4; i++)
#pragma unroll
        for (int t = 0; t < 4; t++)
#pragma unroll
            for (int u = 0; u < 4; u++) acc[i][t][u] = 0.f;

    for (int kk = 0; kk < 128; kk += 32) {
#pragma unroll
        for (int q = 0; q < 4; q++) {
            int fid = tid + q * 256;
            int row = fid >> 3;
            int c4  = fid & 7;
            int gr  = gRow0 + row;
            float4 v = make_float4(0.f, 0.f, 0.f, 0.f);
            if (gr < M) v = *(const float4*)(A + (size_t)gr * 128 + kk + c4 * 4);
            int mi = row >> 4, rr = row & 15;
            int ki = c4 >> 1;
            int j  = (rr >> 3) | ((c4 & 1) << 1);
            uint4 o;
            o.x = f2tf32(v.x); o.y = f2tf32(v.y); o.z = f2tf32(v.z); o.w = f2tf32(v.w);
            *(uint4*)(&Asp[(ki * 8 + mi) * 128 + j * 32 + (rr & 7) * 4]) = o;
        }
        __syncthreads();
#pragma unroll
        for (int ki = 0; ki < 4; ki++) {
            uint32_t af[4][4];
#pragma unroll
            for (int i = 0; i < 4; i++) {
                const uint32_t* base = &Asp[(ki * 8 + wm * 4 + i) * 128];
                af[i][0] = base[lane];
                af[i][1] = base[32 + lane];
                af[i][2] = base[64 + lane];
                af[i][3] = base[96 + lane];
            }
            uint32_t bf[4][2];
            int kig = (kk >> 3) + ki;
#pragma unroll
            for (int t = 0; t < 4; t++) {
                uint2 b2 = *(const uint2*)(&g_Bperm[(kig * 16 + wn * 4 + t) * 64 + lane * 2]);
                bf[t][0] = b2.x; bf[t][1] = b2.y;
            }
#pragma unroll
            for (int i = 0; i < 4; i++)
#pragma unroll
                for (int t = 0; t < 4; t++) mma_tf32(acc[i][t], af[i], bf[t]);
        }
        __syncthreads();
    }
    int g = lane >> 2, t4 = lane & 3;
#pragma unroll
    for (int i = 0; i < 4; i++) {
        int row0 = gRow0 + (wm * 4 + i) * 16 + g;
        int row1 = row0 + 8;
        float rs0 = 1.f, rs1 = 1.f;
        if (rowscale) {
            if (row0 < M) rs0 = rowscale[row0];
            if (row1 < M) rs1 = rowscale[row1];
        }
#pragma unroll
        for (int t = 0; t < 4; t++) {
            int col = (wn * 4 + t) * 8 + 2 * t4;
            float b0 = bias ? bias[col] : 0.f;
            float b1 = bias ? bias[col + 1] : 0.f;
            if (row0 < M)
                *(__half2*)(Ch + (size_t)row0 * 128 + col) =
                    __floats2half2_rn((acc[i][t][0] + b0) * rs0, (acc[i][t][1] + b1) * rs0);
            if (row1 < M)
                *(__half2*)(Ch + (size_t)row1 * 128 + col) =
                    __floats2half2_rn((acc[i][t][2] + b0) * rs1, (acc[i][t][3] + b1) * rs1);
        }
    }
}

// ---------------- fused GCN: cp.async pipelined gather (warp per node) --------------
__global__ __launch_bounds__(256) void k_gcn(const float* __restrict__ bias) {
    __shared__ __align__(16) __half sb[8][STG][4][HD];   // 32 KB
    int tid = threadIdx.x;
    int wip = tid >> 5, lane = tid & 31;
    int r = blockIdx.x * 8 + wip;                        // grid = 5000 exact
    int beg = g_rowptr[r];
    int cnt = g_deg[r] - 1;
    const __half* xw = g_bufXW;

    // col chunks (one coalesced load per 32 edges, distributed via shfl)
    int win = 0;
    int cur = (lane < cnt) ? g_csrcol[beg + lane] : 0;
    int nxt = (32 + lane < cnt) ? g_csrcol[beg + 32 + lane] : 0;

    // prologue: issue stages 0..STG-1
#pragma unroll
    for (int s = 0; s < STG; s++) {
#pragma unroll
        for (int q = 0; q < 4; q++) {
            int idx = s * 4 + q;
            if (idx < cnt) {
                int c = __shfl_sync(0xffffffffu, idx < 32 ? cur : nxt, idx & 31);
                uint32_t dst = (uint32_t)__cvta_generic_to_shared(&sb[wip][s][q][0]) + lane * 8;
                cp8(dst, xw + (size_t)c * HD + lane * 4);
            }
        }
        cp_commit();
    }

    float dr = g_dinv[r];
    float4 acc = h8_to_f4(*(const uint2*)(xw + (size_t)r * HD + lane * 4));  // self loop

    int nst = (cnt + 3) >> 2;
    for (int s = 0; s < nst; s++) {
        int j0 = s * 4;
        if ((j0 >> 5) != win) {                          // advance col window
            win++;
            cur = nxt;
            int i = (win + 1) * 32 + lane;
            nxt = (i < cnt) ? g_csrcol[beg + i] : 0;
        }
        cp_wait();
        int slot = s & (STG - 1);
        if (j0 + 4 <= cnt) {
            uint2 u0 = *(uint2*)(&sb[wip][slot][0][lane * 4]);
            uint2 u1 = *(uint2*)(&sb[wip][slot][1][lane * 4]);
            uint2 u2 = *(uint2*)(&sb[wip][slot][2][lane * 4]);
            uint2 u3 = *(uint2*)(&sb[wip][slot][3][lane * 4]);
            float4 v0 = h8_to_f4(u0), v1 = h8_to_f4(u1);
            float4 v2 = h8_to_f4(u2), v3 = h8_to_f4(u3);
            acc.x += (v0.x + v1.x) + (v2.x + v3.x);
            acc.y += (v0.y + v1.y) + (v2.y + v3.y);
            acc.z += (v0.z + v1.z) + (v2.z + v3.z);
            acc.w += (v0.w + v1.w) + (v2.w + v3.w);
        } else {
            for (int idx = j0; idx < cnt; idx++) {
                uint2 u = *(uint2*)(&sb[wip][slot][idx - j0][lane * 4]);
                float4 v = h8_to_f4(u);
                acc.x += v.x; acc.y += v.y; acc.z += v.z; acc.w += v.w;
            }
        }
        // issue stage s+STG (same slot just consumed)
        int ji = (s + STG) * 4;
#pragma unroll
        for (int q = 0; q < 4; q++) {
            int idx = ji + q;
            if (idx < cnt) {
                int sel = ((idx >> 5) != win) ? nxt : cur;
                int c = __shfl_sync(0xffffffffu, sel, idx & 31);
                uint32_t dst = (uint32_t)__cvta_generic_to_shared(&sb[wip][slot][q][0]) + lane * 8;
                cp8(dst, xw + (size_t)c * HD + lane * 4);
            }
        }
        cp_commit();
    }
    float4 b = *(const float4*)(bias + lane * 4);
    acc.x = fmaxf(acc.x * dr + b.x, 0.f);
    acc.y = fmaxf(acc.y * dr + b.y, 0.f);
    acc.z = fmaxf(acc.z * dr + b.z, 0.f);
    acc.w = fmaxf(acc.w * dr + b.w, 0.f);
    *(float4*)(g_bufACC + (size_t)r * HD + lane * 4) = acc;
}

// ---------------- fused GAT: cp.async pipelined online softmax (warp per node) ------
__global__ __launch_bounds__(256) void k_gat() {
    __shared__ __align__(16) __half sb[8][STG][4][HD];   // 32 KB
    int tid = threadIdx.x;
    int wip = tid >> 5, lane = tid & 31;
    int r = blockIdx.x * 8 + wip;
    int beg = g_rowptr[r];
    int cnt = g_deg[r] - 1;
    const __half* hh = g_bufHH;

    int win = 0;
    int cur = (lane < cnt) ? g_csrcol[beg + lane] : 0;
    int nxt = (32 + lane < cnt) ? g_csrcol[beg + 32 + lane] : 0;

#pragma unroll
    for (int s = 0; s < STG; s++) {
#pragma unroll
        for (int q = 0; q < 4; q++) {
            int idx = s * 4 + q;
            if (idx < cnt) {
                int c = __shfl_sync(0xffffffffu, idx < 32 ? cur : nxt, idx & 31);
                uint32_t dst = (uint32_t)__cvta_generic_to_shared(&sb[wip][s][q][0]) + lane * 8;
                cp8(dst, hh + (size_t)c * HD + lane * 4);
            }
        }
        cp_commit();
    }

    float4 hr = h8_to_f4(*(const uint2*)(hh + (size_t)r * HD + lane * 4));
    float m = warp_sum(hr.x * hr.x + hr.y * hr.y + hr.z * hr.z + hr.w * hr.w);
    float denom = 1.f;
    float4 acc = hr;

    int nst = (cnt + 3) >> 2;
    for (int s = 0; s < nst; s++) {
        int j0 = s * 4;
        if ((j0 >> 5) != win) {
            win++;
            cur = nxt;
            int i = (win + 1) * 32 + lane;
            nxt = (i < cnt) ? g_csrcol[beg + i] : 0;
        }
        cp_wait();
        int slot = s & (STG - 1);
        if (j0 + 4 <= cnt) {
            int c0 = __shfl_sync(0xffffffffu, cur, (j0 + 0) & 31);
            int c1 = __shfl_sync(0xffffffffu, cur, (j0 + 1) & 31);
            int c2 = __shfl_sync(0xffffffffu, cur, (j0 + 2) & 31);
            int c3 = __shfl_sync(0xffffffffu, cur, (j0 + 3) & 31);
            float4 h0 = h8_to_f4(*(uint2*)(&sb[wip][slot][0][lane * 4]));
            float4 h1 = h8_to_f4(*(uint2*)(&sb[wip][slot][1][lane * 4]));
            float4 h2 = h8_to_f4(*(uint2*)(&sb[wip][slot][2][lane * 4]));
            float4 h3 = h8_to_f4(*(uint2*)(&sb[wip][slot][3][lane * 4]));
            float d0 = hr.x * h0.x + hr.y * h0.y + hr.z * h0.z + hr.w * h0.w;
            float d1 = hr.x * h1.x + hr.y * h1.y + hr.z * h1.z + hr.w * h1.w;
            float d2 = hr.x * h2.x + hr.y * h2.y + hr.z * h2.z + hr.w * h2.w;
            float d3 = hr.x * h3.x + hr.y * h3.y + hr.z * h3.z + hr.w * h3.w;
#pragma unroll
            for (int o = 16; o; o >>= 1) {
                d0 += __shfl_xor_sync(0xffffffffu, d0, o);
                d1 += __shfl_xor_sync(0xffffffffu, d1, o);
                d2 += __shfl_xor_sync(0xffffffffu, d2, o);
                d3 += __shfl_xor_sync(0xffffffffu, d3, o);
            }
            float a0 = (c0 == r) ? -CUDART_INF_F : ((d0 > 0.f) ? d0 : 0.2f * d0);
            float a1 = (c1 == r) ? -CUDART_INF_F : ((d1 > 0.f) ? d1 : 0.2f * d1);
            float a2 = (c2 == r) ? -CUDART_INF_F : ((d2 > 0.f) ? d2 : 0.2f * d2);
            float a3 = (c3 == r) ? -CUDART_INF_F : ((d3 > 0.f) ? d3 : 0.2f * d3);
            float mblk = fmaxf(fmaxf(a0, a1), fmaxf(a2, a3));
            if (mblk > m) {                              // warp-uniform, rare
                float sc = __expf(m - mblk);
                denom *= sc;
                acc.x *= sc; acc.y *= sc; acc.z *= sc; acc.w *= sc;
                m = mblk;
            }
            float e0 = __expf(a0 - m);
            float e1 = __expf(a1 - m);
            float e2 = __expf(a2 - m);
            float e3 = __expf(a3 - m);
            denom += (e0 + e1) + (e2 + e3);
            acc.x += (e0 * h0.x + e1 * h1.x) + (e2 * h2.x + e3 * h3.x);
            acc.y += (e0 * h0.y + e1 * h1.y) + (e2 * h2.y + e3 * h3.y);
            acc.z += (e0 * h0.z + e1 * h1.z) + (e2 * h2.z + e3 * h3.z);
            acc.w += (e0 * h0.w + e1 * h1.w) + (e2 * h2.w + e3 * h3.w);
        } else {
            for (int idx = j0; idx < cnt; idx++) {
                int c = __shfl_sync(0xffffffffu, cur, idx & 31);
                if (c == r) continue;
                float4 hc = h8_to_f4(*(uint2*)(&sb[wip][slot][idx - j0][lane * 4]));
                float d = warp_sum(hr.x * hc.x + hr.y * hc.y + hr.z * hc.z + hr.w * hc.w);
                float al = (d > 0.f) ? d : 0.2f * d;
                if (al > m) {
                    float sc = __expf(m - al);
                    denom *= sc;
                    acc.x *= sc; acc.y *= sc; acc.z *= sc; acc.w *= sc;
                    m = al;
                }
                float e = __expf(al - m);
                denom += e;
                acc.x += e * hc.x;
                acc.y += e * hc.y;
                acc.z += e * hc.z;
                acc.w += e * hc.w;
            }
        }
        int ji = (s + STG) * 4;
#pragma unroll
        for (int q = 0; q < 4; q++) {
            int idx = ji + q;
            if (idx < cnt) {
                int sel = ((idx >> 5) != win) ? nxt : cur;
                int c = __shfl_sync(0xffffffffu, sel, idx & 31);
                uint32_t dst = (uint32_t)__cvta_generic_to_shared(&sb[wip][slot][q][0]) + lane * 8;
                cp8(dst, hh + (size_t)c * HD + lane * 4);
            }
        }
        cp_commit();
    }
    float inv = 1.f / fmaxf(denom, 1e-16f);
    acc.x *= inv; acc.y *= inv; acc.z *= inv; acc.w *= inv;
    *(float4*)(g_bufOUT + (size_t)r * HD + lane * 4) = acc;
}

// ---------------- final mean pool ----------------
__global__ void k_zero_out(float* out) {
    int t = threadIdx.x;
    if (t < 2 * HD) out[t] = 0.f;
}
__global__ void k_mean(float* __restrict__ out) {
    int col = threadIdx.x;                    // 128 threads
    float s = 0.f;
    for (int i = blockIdx.x; i < NND; i += gridDim.x)
        s += g_bufOUT[(size_t)i * HD + col];
    s *= (1.0f / NND);
    atomicAdd(&out[col], s);
    atomicAdd(&out[col + HD], s);
}

// ---------------- launch ----------------
extern "C" void kernel_launch(void* const* d_in, const int* in_sizes, int n_in,
                              void* d_out, int out_size) {
    const float* x   = (const float*)d_in[0];
    const int*   ei  = (const int*)d_in[1];     // int32 (JAX x64 disabled)
    int E = in_sizes[1] / 2;
    const int* row = ei;
    const int* col = ei + E;
    const float* Wg[3] = {(const float*)d_in[2], (const float*)d_in[6],  (const float*)d_in[10]};
    const float* bg[3] = {(const float*)d_in[3], (const float*)d_in[7],  (const float*)d_in[11]};
    const float* Wa[3] = {(const float*)d_in[4], (const float*)d_in[8],  (const float*)d_in[12]};
    const float* ba[3] = {(const float*)d_in[5], (const float*)d_in[9],  (const float*)d_in[13]};
    float* out = (float*)d_out;

    __half *pXW, *pHH;
    float *pACC, *pOUT, *pDinv;
    cudaGetSymbolAddress((void**)&pXW,  g_bufXW);
    cudaGetSymbolAddress((void**)&pHH,  g_bufHH);
    cudaGetSymbolAddress((void**)&pACC, g_bufACC);
    cudaGetSymbolAddress((void**)&pOUT, g_bufOUT);
    cudaGetSymbolAddress((void**)&pDinv, g_dinv);

    const int TB = 256;
    int gN  = (NND + TB - 1) / TB;              // 157
    int gE  = (E + TB - 1) / TB;
    int gNw = NND / 8;                          // 5000, exact (warp per node)
    int gGemm = (NND + 127) / 128;              // 313

    k_deg_init<<<gN, TB>>>();
    k_deg_count<<<gE, TB>>>(row, E);
    k_scanA<<<gN, TB>>>();                      // also computes dinv
    k_scanB<<<1, TB>>>(gN);
    k_scanC<<<gN, TB>>>();
    k_fill<<<gE, TB>>>(row, col, E);

    const float* cur = x;
    for (int l = 0; l < 3; l++) {
        k_bperm<<<64, TB>>>(Wg[l], l > 0 ? 1 : 0);
        k_gemm_tf32<<<gGemm, TB>>>(cur, nullptr, pDinv, pXW, NND);   // xwS = xw * dinv
        k_gcn<<<gNw, TB>>>(bg[l]);
        k_bperm<<<64, TB>>>(Wa[l], 0);
        k_gemm_tf32<<<gGemm, TB>>>(pACC, ba[l], nullptr, pHH, NND);
        k_gat<<<gNw, TB>>>();
        cur = pOUT;
    }
    k_zero_out<<<1, TB>>>(out);
    k_mean<<<512, HD>>>(out);
}

// round 13
// speedup vs baseline: 1.2413x; 1.2413x over previous
#include <cuda_runtime.h>
#include <cuda_fp16.h>
#include <cstdint>
#include <math_constants.h>

#define NND 40000
#define HD  128
#define EED 640000

// ---------------- scratch (device globals: allocation-free) ----------------
__device__ __half   g_bufXW [(size_t)NND * HD];   // GCN GEMM out, fp16 (gathered)
__device__ __half   g_bufHH [(size_t)NND * HD];   // GAT GEMM out, fp16 (gathered)
__device__ float    g_bufACC[(size_t)NND * HD];   // relu(GCN) out, fp32 (GEMM input)
__device__ float    g_bufOUT[(size_t)NND * HD];   // GAT out, fp32 (GEMM input / pool)
__device__ int      g_deg   [NND];
__device__ float    g_dinv  [NND];
__device__ int      g_rowptr[NND];
__device__ int      g_cursor[NND];
__device__ int      g_rowtmp[NND];
__device__ int      g_bsum  [256];
__device__ int      g_boff  [256];
__device__ int      g_csrcol[EED];
__device__ uint32_t g_Bperm [HD * HD];

// ---------------- helpers ----------------
__device__ __forceinline__ void h16_to_f8(uint4 u, float* f) {
    float2 p0 = __half22float2(*(__half2*)&u.x);
    float2 p1 = __half22float2(*(__half2*)&u.y);
    float2 p2 = __half22float2(*(__half2*)&u.z);
    float2 p3 = __half22float2(*(__half2*)&u.w);
    f[0] = p0.x; f[1] = p0.y; f[2] = p1.x; f[3] = p1.y;
    f[4] = p2.x; f[5] = p2.y; f[6] = p3.x; f[7] = p3.y;
}

// ---------------- degree / norm ----------------
__global__ void k_deg_init() {
    int i = blockIdx.x * blockDim.x + threadIdx.x;
    if (i < NND) g_deg[i] = 1;
}
__global__ void k_deg_count(const int* __restrict__ row, int E) {
    int e = blockIdx.x * blockDim.x + threadIdx.x;
    if (e < E) atomicAdd(&g_deg[row[e]], 1);
}

// ---------------- hierarchical exclusive scan of (deg-1), + dinv ----------------
__global__ __launch_bounds__(256) void k_scanA() {
    __shared__ int sm[256];
    int tx = threadIdx.x;
    int i = blockIdx.x * 256 + tx;
    int d = (i < NND) ? g_deg[i] : 1;
    if (i < NND) g_dinv[i] = rsqrtf((float)d);
    int v = d - 1;
    if (i >= NND) v = 0;
    sm[tx] = v;
    __syncthreads();
#pragma unroll
    for (int off = 1; off < 256; off <<= 1) {
        int p = (tx >= off) ? sm[tx - off] : 0;
        __syncthreads();
        sm[tx] += p;
        __syncthreads();
    }
    if (i < NND) g_rowtmp[i] = sm[tx] - v;
    if (tx == 255) g_bsum[blockIdx.x] = sm[255];
}
__global__ __launch_bounds__(256) void k_scanB(int nb) {
    __shared__ int sm[256];
    int tx = threadIdx.x;
    int v = (tx < nb) ? g_bsum[tx] : 0;
    sm[tx] = v;
    __syncthreads();
#pragma unroll
    for (int off = 1; off < 256; off <<= 1) {
        int p = (tx >= off) ? sm[tx - off] : 0;
        __syncthreads();
        sm[tx] += p;
        __syncthreads();
    }
    g_boff[tx] = sm[tx] - v;
}
__global__ void k_scanC() {
    int i = blockIdx.x * blockDim.x + threadIdx.x;
    if (i < NND) {
        int rp = g_rowtmp[i] + g_boff[i >> 8];
        g_rowptr[i] = rp;
        g_cursor[i] = rp;
    }
}
__global__ void k_fill(const int* __restrict__ row, const int* __restrict__ col, int E) {
    int e = blockIdx.x * blockDim.x + threadIdx.x;
    if (e >= E) return;
    int r = row[e];
    int pos = atomicAdd(&g_cursor[r], 1);
    g_csrcol[pos] = col[e];
}

// ---------------- weight preconvert: (fold) + tf32 + fragment permute ----------------
__device__ __forceinline__ uint32_t f2tf32(float f) {
    uint32_t u;
    asm("cvt.rna.tf32.f32 %0, %1;" : "=r"(u) : "f"(f));
    return u;
}
__global__ void k_bperm(const float* __restrict__ W, int fold) {
    int t = blockIdx.x * blockDim.x + threadIdx.x;
    if (t >= HD * HD) return;
    int k = t >> 7, n = t & 127;
    float v = W[t];
    if (fold) v += W[t + HD * HD];
    int ki = k >> 3, ni = n >> 3, kk = k & 7, nn = n & 7;
    int l = (nn << 2) | (kk & 3);
    int j = kk >> 2;
    g_Bperm[(ki * 16 + ni) * 64 + l * 2 + j] = f2tf32(v);
}

// ---------------- TF32 tensor-core GEMM: Ch[M,128] = A[M,128] @ Bperm (fp16 out) ----
__device__ __forceinline__ void mma_tf32(float* d, const uint32_t* a, const uint32_t* b) {
    asm volatile(
        "mma.sync.aligned.m16n8k8.row.col.f32.tf32.tf32.f32 "
        "{%0,%1,%2,%3}, {%4,%5,%6,%7}, {%8,%9}, {%0,%1,%2,%3};"
        : "+f"(d[0]), "+f"(d[1]), "+f"(d[2]), "+f"(d[3])
        : "r"(a[0]), "r"(a[1]), "r"(a[2]), "r"(a[3]), "r"(b[0]), "r"(b[1]));
}
__global__ __launch_bounds__(256) void k_gemm_tf32(const float* __restrict__ A,
                                                   const float* __restrict__ bias,
                                                   const float* __restrict__ rowscale,
                                                   __half* __restrict__ Ch, int M) {
    __shared__ uint32_t Asp[32 * 128];
    int tid = threadIdx.x;
    int lane = tid & 31;
    int w = tid >> 5;
    int wm = w >> 2, wn = w & 3;
    int gRow0 = blockIdx.x * 128;
    float acc[4][4][4];
#pragma unroll
    for (int i = 0; i < 4; i++)
#pragma unroll
        for (int t = 0; t < 4; t++)
#pragma unroll
            for (int u = 0; u < 4; u++) acc[i][t][u] = 0.f;

    for (int kk = 0; kk < 128; kk += 32) {
#pragma unroll
        for (int q = 0; q < 4; q++) {
            int fid = tid + q * 256;
            int row = fid >> 3;
            int c4  = fid & 7;
            int gr  = gRow0 + row;
            float4 v = make_float4(0.f, 0.f, 0.f, 0.f);
            if (gr < M) v = *(const float4*)(A + (size_t)gr * 128 + kk + c4 * 4);
            int mi = row >> 4, rr = row & 15;
            int ki = c4 >> 1;
            int j  = (rr >> 3) | ((c4 & 1) << 1);
            uint4 o;
            o.x = f2tf32(v.x); o.y = f2tf32(v.y); o.z = f2tf32(v.z); o.w = f2tf32(v.w);
            *(uint4*)(&Asp[(ki * 8 + mi) * 128 + j * 32 + (rr & 7) * 4]) = o;
        }
        __syncthreads();
#pragma unroll
        for (int ki = 0; ki < 4; ki++) {
            uint32_t af[4][4];
#pragma unroll
            for (int i = 0; i < 4; i++) {
                const uint32_t* base = &Asp[(ki * 8 + wm * 4 + i) * 128];
                af[i][0] = base[lane];
                af[i][1] = base[32 + lane];
                af[i][2] = base[64 + lane];
                af[i][3] = base[96 + lane];
            }
            uint32_t bf[4][2];
            int kig = (kk >> 3) + ki;
#pragma unroll
            for (int t = 0; t < 4; t++) {
                uint2 b2 = *(const uint2*)(&g_Bperm[(kig * 16 + wn * 4 + t) * 64 + lane * 2]);
                bf[t][0] = b2.x; bf[t][1] = b2.y;
            }
#pragma unroll
            for (int i = 0; i < 4; i++)
#pragma unroll
                for (int t = 0; t < 4; t++) mma_tf32(acc[i][t], af[i], bf[t]);
        }
        __syncthreads();
    }
    int g = lane >> 2, t4 = lane & 3;
#pragma unroll
    for (int i = 0; i < 4; i++) {
        int row0 = gRow0 + (wm * 4 + i) * 16 + g;
        int row1 = row0 + 8;
        float rs0 = 1.f, rs1 = 1.f;
        if (rowscale) {
            if (row0 < M) rs0 = rowscale[row0];
            if (row1 < M) rs1 = rowscale[row1];
        }
#pragma unroll
        for (int t = 0; t < 4; t++) {
            int col = (wn * 4 + t) * 8 + 2 * t4;
            float b0 = bias ? bias[col] : 0.f;
            float b1 = bias ? bias[col + 1] : 0.f;
            if (row0 < M)
                *(__half2*)(Ch + (size_t)row0 * 128 + col) =
                    __floats2half2_rn((acc[i][t][0] + b0) * rs0, (acc[i][t][1] + b1) * rs0);
            if (row1 < M)
                *(__half2*)(Ch + (size_t)row1 * 128 + col) =
                    __floats2half2_rn((acc[i][t][2] + b0) * rs1, (acc[i][t][3] + b1) * rs1);
        }
    }
}

// ---------------- fused GCN: paired-row uint4 gather (warp per node) ----------------
// lanes 0-15 fetch row j (16B/lane), lanes 16-31 fetch row j+1; per-half accumulate,
// merge once at the end. 4 loads in flight = 8 rows.
__global__ __launch_bounds__(256) void k_gcn(const float* __restrict__ bias) {
    int tid = threadIdx.x;
    int lane = tid & 31;
    int l16 = lane & 15;
    int hf = lane >> 4;                                  // 0 or 1
    int r = (blockIdx.x * 256 + tid) >> 5;               // warp per node (grid exact)
    int beg = g_rowptr[r];
    int cnt = g_deg[r] - 1;
    const __half* xw = g_bufXW;
    float f[8], accv[8];
    {   // self loop counted once (half 0 only)
        uint4 us = *(const uint4*)(xw + (size_t)r * HD + l16 * 8);
        h16_to_f8(us, f);
#pragma unroll
        for (int i = 0; i < 8; i++) accv[i] = hf ? 0.f : f[i];
    }
    int j = 0;
    for (; j + 8 <= cnt; j += 8) {
        int c0 = g_csrcol[beg + j + hf];
        int c1 = g_csrcol[beg + j + 2 + hf];
        int c2 = g_csrcol[beg + j + 4 + hf];
        int c3 = g_csrcol[beg + j + 6 + hf];
        uint4 u0 = *(const uint4*)(xw + (size_t)c0 * HD + l16 * 8);
        uint4 u1 = *(const uint4*)(xw + (size_t)c1 * HD + l16 * 8);
        uint4 u2 = *(const uint4*)(xw + (size_t)c2 * HD + l16 * 8);
        uint4 u3 = *(const uint4*)(xw + (size_t)c3 * HD + l16 * 8);
        h16_to_f8(u0, f);
#pragma unroll
        for (int i = 0; i < 8; i++) accv[i] += f[i];
        h16_to_f8(u1, f);
#pragma unroll
        for (int i = 0; i < 8; i++) accv[i] += f[i];
        h16_to_f8(u2, f);
#pragma unroll
        for (int i = 0; i < 8; i++) accv[i] += f[i];
        h16_to_f8(u3, f);
#pragma unroll
        for (int i = 0; i < 8; i++) accv[i] += f[i];
    }
    for (; j < cnt; j += 2) {
        bool v = (j + hf) < cnt;
        int c = v ? g_csrcol[beg + j + hf] : r;          // dummy valid address
        uint4 u = *(const uint4*)(xw + (size_t)c * HD + l16 * 8);
        h16_to_f8(u, f);
        if (v) {
#pragma unroll
            for (int i = 0; i < 8; i++) accv[i] += f[i];
        }
    }
#pragma unroll
    for (int i = 0; i < 8; i++) accv[i] += __shfl_xor_sync(0xffffffffu, accv[i], 16);
    if (hf == 0) {
        float dr = g_dinv[r];
        float4 b0 = *(const float4*)(bias + l16 * 8);
        float4 b1 = *(const float4*)(bias + l16 * 8 + 4);
        float4 o0, o1;
        o0.x = fmaxf(accv[0] * dr + b0.x, 0.f);
        o0.y = fmaxf(accv[1] * dr + b0.y, 0.f);
        o0.z = fmaxf(accv[2] * dr + b0.z, 0.f);
        o0.w = fmaxf(accv[3] * dr + b0.w, 0.f);
        o1.x = fmaxf(accv[4] * dr + b1.x, 0.f);
        o1.y = fmaxf(accv[5] * dr + b1.y, 0.f);
        o1.z = fmaxf(accv[6] * dr + b1.z, 0.f);
        o1.w = fmaxf(accv[7] * dr + b1.w, 0.f);
        *(float4*)(g_bufACC + (size_t)r * HD + l16 * 8)     = o0;
        *(float4*)(g_bufACC + (size_t)r * HD + l16 * 8 + 4) = o1;
    }
}

// ---------------- fused GAT: paired-row gather + lazy-rescale online softmax --------
__global__ __launch_bounds__(256) void k_gat() {
    int tid = threadIdx.x;
    int lane = tid & 31;
    int l16 = lane & 15;
    int hf = lane >> 4;
    int r = (blockIdx.x * 256 + tid) >> 5;
    int beg = g_rowptr[r];
    int cnt = g_deg[r] - 1;
    const __half* hh = g_bufHH;
    float hrf[8];
    {
        uint4 uhr = *(const uint4*)(hh + (size_t)r * HD + l16 * 8);
        h16_to_f8(uhr, hrf);
    }
    // selfdot (both halves compute the same value -> warp-uniform)
    float sd = hrf[0]*hrf[0] + hrf[1]*hrf[1] + hrf[2]*hrf[2] + hrf[3]*hrf[3]
             + hrf[4]*hrf[4] + hrf[5]*hrf[5] + hrf[6]*hrf[6] + hrf[7]*hrf[7];
#pragma unroll
    for (int o = 8; o; o >>= 1) sd += __shfl_xor_sync(0xffffffffu, sd, o);
    float m = sd;                                        // >= 0
    float denom = 1.f;
    float accv[8];
#pragma unroll
    for (int i = 0; i < 8; i++) accv[i] = hf ? 0.f : hrf[i];   // self, weight exp(0)=1

    int j = 0;
    for (; j + 4 <= cnt; j += 4) {
        int cA = g_csrcol[beg + j + hf];
        int cB = g_csrcol[beg + j + 2 + hf];
        uint4 uA = *(const uint4*)(hh + (size_t)cA * HD + l16 * 8);
        uint4 uB = *(const uint4*)(hh + (size_t)cB * HD + l16 * 8);
        float fA[8], fB[8];
        h16_to_f8(uA, fA);
        h16_to_f8(uB, fB);
        float dA = fA[0]*hrf[0] + fA[1]*hrf[1] + fA[2]*hrf[2] + fA[3]*hrf[3]
                 + fA[4]*hrf[4] + fA[5]*hrf[5] + fA[6]*hrf[6] + fA[7]*hrf[7];
        float dB = fB[0]*hrf[0] + fB[1]*hrf[1] + fB[2]*hrf[2] + fB[3]*hrf[3]
                 + fB[4]*hrf[4] + fB[5]*hrf[5] + fB[6]*hrf[6] + fB[7]*hrf[7];
#pragma unroll
        for (int o = 8; o; o >>= 1) {
            dA += __shfl_xor_sync(0xffffffffu, dA, o);
            dB += __shfl_xor_sync(0xffffffffu, dB, o);
        }
        float amA = (cA == r) ? -CUDART_INF_F : ((dA > 0.f) ? dA : 0.2f * dA);
        float amB = (cB == r) ? -CUDART_INF_F : ((dB > 0.f) ? dB : 0.2f * dB);
        float a0 = __shfl_sync(0xffffffffu, amA, 0);
        float a1 = __shfl_sync(0xffffffffu, amA, 16);
        float a2 = __shfl_sync(0xffffffffu, amB, 0);
        float a3 = __shfl_sync(0xffffffffu, amB, 16);
        float mblk = fmaxf(fmaxf(a0, a1), fmaxf(a2, a3));
        if (mblk > m) {                                  // warp-uniform, rare
            float sc = __expf(m - mblk);
            denom *= sc;
#pragma unroll
            for (int i = 0; i < 8; i++) accv[i] *= sc;
            m = mblk;
        }
        float e0 = __expf(a0 - m);
        float e1 = __expf(a1 - m);
        float e2 = __expf(a2 - m);
        float e3 = __expf(a3 - m);
        denom += (e0 + e1) + (e2 + e3);
        float eA = hf ? e1 : e0;
        float eB = hf ? e3 : e2;
#pragma unroll
        for (int i = 0; i < 8; i++) accv[i] += eA * fA[i] + eB * fB[i];
    }
    for (; j < cnt; j += 2) {
        bool v = (j + hf) < cnt;
        int c = v ? g_csrcol[beg + j + hf] : r;          // invalid -> c==r -> masked
        uint4 u = *(const uint4*)(hh + (size_t)c * HD + l16 * 8);
        float f[8];
        h16_to_f8(u, f);
        float d = f[0]*hrf[0] + f[1]*hrf[1] + f[2]*hrf[2] + f[3]*hrf[3]
                + f[4]*hrf[4] + f[5]*hrf[5] + f[6]*hrf[6] + f[7]*hrf[7];
#pragma unroll
        for (int o = 8; o; o >>= 1) d += __shfl_xor_sync(0xffffffffu, d, o);
        float am = (c == r) ? -CUDART_INF_F : ((d > 0.f) ? d : 0.2f * d);
        float a0 = __shfl_sync(0xffffffffu, am, 0);
        float a1 = __shfl_sync(0xffffffffu, am, 16);
        float mblk = fmaxf(a0, a1);
        if (mblk > m) {
            float sc = __expf(m - mblk);
            denom *= sc;
#pragma unroll
            for (int i = 0; i < 8; i++) accv[i] *= sc;
            m = mblk;
        }
        float e0 = __expf(a0 - m);                       // exp(-inf)=0 handles masks
        float e1 = __expf(a1 - m);
        denom += e0 + e1;
        float em = hf ? e1 : e0;
#pragma unroll
        for (int i = 0; i < 8; i++) accv[i] += em * f[i];
    }
#pragma unroll
    for (int i = 0; i < 8; i++) accv[i] += __shfl_xor_sync(0xffffffffu, accv[i], 16);
    if (hf == 0) {
        float inv = 1.f / fmaxf(denom, 1e-16f);
        float4 o0 = make_float4(accv[0] * inv, accv[1] * inv, accv[2] * inv, accv[3] * inv);
        float4 o1 = make_float4(accv[4] * inv, accv[5] * inv, accv[6] * inv, accv[7] * inv);
        *(float4*)(g_bufOUT + (size_t)r * HD + l16 * 8)     = o0;
        *(float4*)(g_bufOUT + (size_t)r * HD + l16 * 8 + 4) = o1;
    }
}

// ---------------- final mean pool ----------------
__global__ void k_zero_out(float* out) {
    int t = threadIdx.x;
    if (t < 2 * HD) out[t] = 0.f;
}
__global__ void k_mean(float* __restrict__ out) {
    int col = threadIdx.x;                    // 128 threads
    float s = 0.f;
    for (int i = blockIdx.x; i < NND; i += gridDim.x)
        s += g_bufOUT[(size_t)i * HD + col];
    s *= (1.0f / NND);
    atomicAdd(&out[col], s);
    atomicAdd(&out[col + HD], s);
}

// ---------------- launch ----------------
extern "C" void kernel_launch(void* const* d_in, const int* in_sizes, int n_in,
                              void* d_out, int out_size) {
    const float* x   = (const float*)d_in[0];
    const int*   ei  = (const int*)d_in[1];     // int32 (JAX x64 disabled)
    int E = in_sizes[1] / 2;
    const int* row = ei;
    const int* col = ei + E;
    const float* Wg[3] = {(const float*)d_in[2], (const float*)d_in[6],  (const float*)d_in[10]};
    const float* bg[3] = {(const float*)d_in[3], (const float*)d_in[7],  (const float*)d_in[11]};
    const float* Wa[3] = {(const float*)d_in[4], (const float*)d_in[8],  (const float*)d_in[12]};
    const float* ba[3] = {(const float*)d_in[5], (const float*)d_in[9],  (const float*)d_in[13]};
    float* out = (float*)d_out;

    __half *pXW, *pHH;
    float *pACC, *pOUT, *pDinv;
    cudaGetSymbolAddress((void**)&pXW,  g_bufXW);
    cudaGetSymbolAddress((void**)&pHH,  g_bufHH);
    cudaGetSymbolAddress((void**)&pACC, g_bufACC);
    cudaGetSymbolAddress((void**)&pOUT, g_bufOUT);
    cudaGetSymbolAddress((void**)&pDinv, g_dinv);

    const int TB = 256;
    int gN  = (NND + TB - 1) / TB;              // 157
    int gE  = (E + TB - 1) / TB;
    int gNw = NND / 8;                          // 5000 exact (warp per node)
    int gGemm = (NND + 127) / 128;              // 313

    k_deg_init<<<gN, TB>>>();
    k_deg_count<<<gE, TB>>>(row, E);
    k_scanA<<<gN, TB>>>();                      // also computes dinv
    k_scanB<<<1, TB>>>(gN);
    k_scanC<<<gN, TB>>>();
    k_fill<<<gE, TB>>>(row, col, E);

    const float* cur = x;
    for (int l = 0; l < 3; l++) {
        k_bperm<<<64, TB>>>(Wg[l], l > 0 ? 1 : 0);
        k_gemm_tf32<<<gGemm, TB>>>(cur, nullptr, pDinv, pXW, NND);   // xwS = xw * dinv
        k_gcn<<<gNw, TB>>>(bg[l]);
        k_bperm<<<64, TB>>>(Wa[l], 0);
        k_gemm_tf32<<<gGemm, TB>>>(pACC, ba[l], nullptr, pHH, NND);
        k_gat<<<gNw, TB>>>();
        cur = pOUT;
    }
    k_zero_out<<<1, TB>>>(out);
    k_mean<<<512, HD>>>(out);
}

// round 17
// speedup vs baseline: 1.4367x; 1.1575x over previous
#include <cuda_runtime.h>
#include <cuda_fp16.h>
#include <cstdint>
#include <math_constants.h>

#define NND 40000
#define HD  128
#define EED 640000

// ---------------- scratch (device globals: allocation-free) ----------------
__device__ __half   g_Xh   [(size_t)NND * HD];    // x converted to fp16
__device__ __half   g_bufXW [(size_t)NND * HD];   // GCN GEMM out (gathered)
__device__ __half   g_bufHH [(size_t)NND * HD];   // GAT GEMM out (gathered)
__device__ __half   g_bufACC[(size_t)NND * HD];   // relu(GCN) out (GEMM input)
__device__ __half   g_bufOUT[(size_t)NND * HD];   // GAT out (GEMM input / pool)
__device__ int      g_deg   [NND];
__device__ float    g_dinv  [NND];
__device__ int      g_rowptr[NND];
__device__ int      g_cursor[NND];
__device__ int      g_rowtmp[NND];
__device__ int      g_bsum  [256];
__device__ int      g_boff  [256];
__device__ int      g_csrcol[EED];
__device__ __half   g_BpermH[HD * HD];            // fp16 fragment-permuted weight

// ---------------- helpers ----------------
__device__ __forceinline__ void h16_to_f8(uint4 u, float* f) {
    float2 p0 = __half22float2(*(__half2*)&u.x);
    float2 p1 = __half22float2(*(__half2*)&u.y);
    float2 p2 = __half22float2(*(__half2*)&u.z);
    float2 p3 = __half22float2(*(__half2*)&u.w);
    f[0] = p0.x; f[1] = p0.y; f[2] = p1.x; f[3] = p1.y;
    f[4] = p2.x; f[5] = p2.y; f[6] = p3.x; f[7] = p3.y;
}
__device__ __forceinline__ uint4 f8_to_h16(const float* f) {
    uint4 o;
    *(__half2*)&o.x = __floats2half2_rn(f[0], f[1]);
    *(__half2*)&o.y = __floats2half2_rn(f[2], f[3]);
    *(__half2*)&o.z = __floats2half2_rn(f[4], f[5]);
    *(__half2*)&o.w = __floats2half2_rn(f[6], f[7]);
    return o;
}

// ---------------- x -> fp16 ----------------
__global__ void k_x2h(const float* __restrict__ x) {
    int i = blockIdx.x * blockDim.x + threadIdx.x;   // 8 floats per thread
    if (i >= NND * HD / 8) return;
    float4 a = *(const float4*)(x + i * 8);
    float4 b = *(const float4*)(x + i * 8 + 4);
    float f[8] = {a.x, a.y, a.z, a.w, b.x, b.y, b.z, b.w};
    *(uint4*)(g_Xh + i * 8) = f8_to_h16(f);
}

// ---------------- degree / norm ----------------
__global__ void k_deg_init() {
    int i = blockIdx.x * blockDim.x + threadIdx.x;
    if (i < NND) g_deg[i] = 1;
}
__global__ void k_deg_count(const int* __restrict__ row, int E) {
    int e = blockIdx.x * blockDim.x + threadIdx.x;
    if (e < E) atomicAdd(&g_deg[row[e]], 1);
}

// ---------------- hierarchical exclusive scan of (deg-1), + dinv ----------------
__global__ __launch_bounds__(256) void k_scanA() {
    __shared__ int sm[256];
    int tx = threadIdx.x;
    int i = blockIdx.x * 256 + tx;
    int d = (i < NND) ? g_deg[i] : 1;
    if (i < NND) g_dinv[i] = rsqrtf((float)d);
    int v = d - 1;
    if (i >= NND) v = 0;
    sm[tx] = v;
    __syncthreads();
#pragma unroll
    for (int off = 1; off < 256; off <<= 1) {
        int p = (tx >= off) ? sm[tx - off] : 0;
        __syncthreads();
        sm[tx] += p;
        __syncthreads();
    }
    if (i < NND) g_rowtmp[i] = sm[tx] - v;
    if (tx == 255) g_bsum[blockIdx.x] = sm[255];
}
__global__ __launch_bounds__(256) void k_scanB(int nb) {
    __shared__ int sm[256];
    int tx = threadIdx.x;
    int v = (tx < nb) ? g_bsum[tx] : 0;
    sm[tx] = v;
    __syncthreads();
#pragma unroll
    for (int off = 1; off < 256; off <<= 1) {
        int p = (tx >= off) ? sm[tx - off] : 0;
        __syncthreads();
        sm[tx] += p;
        __syncthreads();
    }
    g_boff[tx] = sm[tx] - v;
}
__global__ void k_scanC() {
    int i = blockIdx.x * blockDim.x + threadIdx.x;
    if (i < NND) {
        int rp = g_rowtmp[i] + g_boff[i >> 8];
        g_rowptr[i] = rp;
        g_cursor[i] = rp;
    }
}
__global__ void k_fill(const int* __restrict__ row, const int* __restrict__ col, int E) {
    int e = blockIdx.x * blockDim.x + threadIdx.x;
    if (e >= E) return;
    int r = row[e];
    int pos = atomicAdd(&g_cursor[r], 1);
    g_csrcol[pos] = col[e];
}

// ---------------- weight preconvert: (fold) + fp16 + m16n8k16 fragment permute ------
// B fragment (col-major n8k16): lane=(nn<<2)|((kk>>1)&3), reg=kk>>3, halfsel=kk&1
__global__ void k_bperm(const float* __restrict__ W, int fold) {
    int t = blockIdx.x * blockDim.x + threadIdx.x;
    if (t >= HD * HD) return;
    int k = t >> 7, n = t & 127;
    float v = W[t];
    if (fold) v += W[t + HD * HD];
    int ki = k >> 4, kk = k & 15, ni = n >> 3, nn = n & 7;
    int lane = (nn << 2) | ((kk >> 1) & 3);
    int reg = kk >> 3;
    int idx = ((ki * 16 + ni) * 64 + lane * 2 + reg) * 2 + (kk & 1);
    g_BpermH[idx] = __float2half(v);
}

// ---------------- FP16 tensor-core GEMM: Ch[M,128] = A[M,128] @ BpermH --------------
// A fragment layout in smem: Asp[atom(ki*8+mi)][lane][reg0..3] (uint4 per lane)
__device__ __forceinline__ void mma_f16(float* d, const uint32_t* a, const uint32_t* b) {
    asm volatile(
        "mma.sync.aligned.m16n8k16.row.col.f32.f16.f16.f32 "
        "{%0,%1,%2,%3}, {%4,%5,%6,%7}, {%8,%9}, {%0,%1,%2,%3};"
        : "+f"(d[0]), "+f"(d[1]), "+f"(d[2]), "+f"(d[3])
        : "r"(a[0]), "r"(a[1]), "r"(a[2]), "r"(a[3]), "r"(b[0]), "r"(b[1]));
}
__global__ __launch_bounds__(256) void k_gemm_f16(const __half* __restrict__ A,
                                                  const float* __restrict__ bias,
                                                  const float* __restrict__ rowscale,
                                                  __half* __restrict__ Ch, int M) {
    __shared__ uint32_t Asp[16][32][4];   // 8 KB: [atom][lane][reg]
    int tid = threadIdx.x;
    int lane = tid & 31;
    int w = tid >> 5;
    int wm = w >> 2, wn = w & 3;          // warps 2(m) x 4(n)
    int gRow0 = blockIdx.x * 128;
    float acc[4][4][4];
#pragma unroll
    for (int i = 0; i < 4; i++)
#pragma unroll
        for (int t = 0; t < 4; t++)
#pragma unroll
            for (int u = 0; u < 4; u++) acc[i][t][u] = 0.f;

    const uint32_t* Bp = (const uint32_t*)g_BpermH;

    for (int kk = 0; kk < 128; kk += 32) {
        // stage A chunk [128 rows x 32 halves]: pure copy, no conversion
#pragma unroll
        for (int q = 0; q < 2; q++) {
            int fid = tid + q * 256;      // 0..511
            int row = fid >> 2;           // 0..127
            int c8  = fid & 3;            // 8-half group within chunk
            int gr  = gRow0 + row;
            uint4 v = make_uint4(0u, 0u, 0u, 0u);
            if (gr < M) v = *(const uint4*)(A + (size_t)gr * 128 + kk + c8 * 8);
            int atom = (c8 >> 1) * 8 + (row >> 4);
            int reg  = ((row >> 3) & 1) | ((c8 & 1) << 1);
            int lb   = (row & 7) * 4;     // lane base (4 consecutive lanes, pairs p=0..3)
            Asp[atom][lb + 0][reg] = v.x;
            Asp[atom][lb + 1][reg] = v.y;
            Asp[atom][lb + 2][reg] = v.z;
            Asp[atom][lb + 3][reg] = v.w;
        }
        __syncthreads();
#pragma unroll
        for (int ki = 0; ki < 2; ki++) {
            int kig = (kk >> 4) + ki;     // global k16 index
            uint32_t af[4][4];
#pragma unroll
            for (int i = 0; i < 4; i++) {
                uint4 a4 = *(const uint4*)&Asp[ki * 8 + wm * 4 + i][lane][0];
                af[i][0] = a4.x; af[i][1] = a4.y; af[i][2] = a4.z; af[i][3] = a4.w;
            }
            uint32_t bf[4][2];
#pragma unroll
            for (int t = 0; t < 4; t++) {
                uint2 b2 = *(const uint2*)(&Bp[(kig * 16 + wn * 4 + t) * 64 + lane * 2]);
                bf[t][0] = b2.x; bf[t][1] = b2.y;
            }
#pragma unroll
            for (int i = 0; i < 4; i++)
#pragma unroll
                for (int t = 0; t < 4; t++) mma_f16(acc[i][t], af[i], bf[t]);
        }
        __syncthreads();
    }
    int g = lane >> 2, t4 = lane & 3;
#pragma unroll
    for (int i = 0; i < 4; i++) {
        int row0 = gRow0 + (wm * 4 + i) * 16 + g;
        int row1 = row0 + 8;
        float rs0 = 1.f, rs1 = 1.f;
        if (rowscale) {
            if (row0 < M) rs0 = rowscale[row0];
            if (row1 < M) rs1 = rowscale[row1];
        }
#pragma unroll
        for (int t = 0; t < 4; t++) {
            int col = (wn * 4 + t) * 8 + 2 * t4;
            float b0 = bias ? bias[col] : 0.f;
            float b1 = bias ? bias[col + 1] : 0.f;
            if (row0 < M)
                *(__half2*)(Ch + (size_t)row0 * 128 + col) =
                    __floats2half2_rn((acc[i][t][0] + b0) * rs0, (acc[i][t][1] + b1) * rs0);
            if (row1 < M)
                *(__half2*)(Ch + (size_t)row1 * 128 + col) =
                    __floats2half2_rn((acc[i][t][2] + b0) * rs1, (acc[i][t][3] + b1) * rs1);
        }
    }
}

// ---------------- fused GCN: paired-row uint4 gather (warp per node) ----------------
__global__ __launch_bounds__(256) void k_gcn(const float* __restrict__ bias) {
    int tid = threadIdx.x;
    int lane = tid & 31;
    int l16 = lane & 15;
    int hf = lane >> 4;
    int r = (blockIdx.x * 256 + tid) >> 5;
    int beg = g_rowptr[r];
    int cnt = g_deg[r] - 1;
    const __half* xw = g_bufXW;
    float f[8], accv[8];
    {
        uint4 us = *(const uint4*)(xw + (size_t)r * HD + l16 * 8);
        h16_to_f8(us, f);
#pragma unroll
        for (int i = 0; i < 8; i++) accv[i] = hf ? 0.f : f[i];
    }
    int j = 0;
    for (; j + 8 <= cnt; j += 8) {
        int c0 = g_csrcol[beg + j + hf];
        int c1 = g_csrcol[beg + j + 2 + hf];
        int c2 = g_csrcol[beg + j + 4 + hf];
        int c3 = g_csrcol[beg + j + 6 + hf];
        uint4 u0 = *(const uint4*)(xw + (size_t)c0 * HD + l16 * 8);
        uint4 u1 = *(const uint4*)(xw + (size_t)c1 * HD + l16 * 8);
        uint4 u2 = *(const uint4*)(xw + (size_t)c2 * HD + l16 * 8);
        uint4 u3 = *(const uint4*)(xw + (size_t)c3 * HD + l16 * 8);
        h16_to_f8(u0, f);
#pragma unroll
        for (int i = 0; i < 8; i++) accv[i] += f[i];
        h16_to_f8(u1, f);
#pragma unroll
        for (int i = 0; i < 8; i++) accv[i] += f[i];
        h16_to_f8(u2, f);
#pragma unroll
        for (int i = 0; i < 8; i++) accv[i] += f[i];
        h16_to_f8(u3, f);
#pragma unroll
        for (int i = 0; i < 8; i++) accv[i] += f[i];
    }
    for (; j < cnt; j += 2) {
        bool v = (j + hf) < cnt;
        int c = v ? g_csrcol[beg + j + hf] : r;
        uint4 u = *(const uint4*)(xw + (size_t)c * HD + l16 * 8);
        h16_to_f8(u, f);
        if (v) {
#pragma unroll
            for (int i = 0; i < 8; i++) accv[i] += f[i];
        }
    }
#pragma unroll
    for (int i = 0; i < 8; i++) accv[i] += __shfl_xor_sync(0xffffffffu, accv[i], 16);
    if (hf == 0) {
        float dr = g_dinv[r];
        float4 b0 = *(const float4*)(bias + l16 * 8);
        float4 b1 = *(const float4*)(bias + l16 * 8 + 4);
        float o[8];
        o[0] = fmaxf(accv[0] * dr + b0.x, 0.f);
        o[1] = fmaxf(accv[1] * dr + b0.y, 0.f);
        o[2] = fmaxf(accv[2] * dr + b0.z, 0.f);
        o[3] = fmaxf(accv[3] * dr + b0.w, 0.f);
        o[4] = fmaxf(accv[4] * dr + b1.x, 0.f);
        o[5] = fmaxf(accv[5] * dr + b1.y, 0.f);
        o[6] = fmaxf(accv[6] * dr + b1.z, 0.f);
        o[7] = fmaxf(accv[7] * dr + b1.w, 0.f);
        *(uint4*)(g_bufACC + (size_t)r * HD + l16 * 8) = f8_to_h16(o);
    }
}

// ---------------- fused GAT: paired-row gather + lazy-rescale online softmax --------
__global__ __launch_bounds__(256) void k_gat() {
    int tid = threadIdx.x;
    int lane = tid & 31;
    int l16 = lane & 15;
    int hf = lane >> 4;
    int r = (blockIdx.x * 256 + tid) >> 5;
    int beg = g_rowptr[r];
    int cnt = g_deg[r] - 1;
    const __half* hh = g_bufHH;
    float hrf[8];
    {
        uint4 uhr = *(const uint4*)(hh + (size_t)r * HD + l16 * 8);
        h16_to_f8(uhr, hrf);
    }
    float sd = hrf[0]*hrf[0] + hrf[1]*hrf[1] + hrf[2]*hrf[2] + hrf[3]*hrf[3]
             + hrf[4]*hrf[4] + hrf[5]*hrf[5] + hrf[6]*hrf[6] + hrf[7]*hrf[7];
#pragma unroll
    for (int o = 8; o; o >>= 1) sd += __shfl_xor_sync(0xffffffffu, sd, o);
    float m = sd;
    float denom = 1.f;
    float accv[8];
#pragma unroll
    for (int i = 0; i < 8; i++) accv[i] = hf ? 0.f : hrf[i];

    int j = 0;
    for (; j + 4 <= cnt; j += 4) {
        int cA = g_csrcol[beg + j + hf];
        int cB = g_csrcol[beg + j + 2 + hf];
        uint4 uA = *(const uint4*)(hh + (size_t)cA * HD + l16 * 8);
        uint4 uB = *(const uint4*)(hh + (size_t)cB * HD + l16 * 8);
        float fA[8], fB[8];
        h16_to_f8(uA, fA);
        h16_to_f8(uB, fB);
        float dA = fA[0]*hrf[0] + fA[1]*hrf[1] + fA[2]*hrf[2] + fA[3]*hrf[3]
                 + fA[4]*hrf[4] + fA[5]*hrf[5] + fA[6]*hrf[6] + fA[7]*hrf[7];
        float dB = fB[0]*hrf[0] + fB[1]*hrf[1] + fB[2]*hrf[2] + fB[3]*hrf[3]
                 + fB[4]*hrf[4] + fB[5]*hrf[5] + fB[6]*hrf[6] + fB[7]*hrf[7];
#pragma unroll
        for (int o = 8; o; o >>= 1) {
            dA += __shfl_xor_sync(0xffffffffu, dA, o);
            dB += __shfl_xor_sync(0xffffffffu, dB, o);
        }
        float amA = (cA == r) ? -CUDART_INF_F : ((dA > 0.f) ? dA : 0.2f * dA);
        float amB = (cB == r) ? -CUDART_INF_F : ((dB > 0.f) ? dB : 0.2f * dB);
        float a0 = __shfl_sync(0xffffffffu, amA, 0);
        float a1 = __shfl_sync(0xffffffffu, amA, 16);
        float a2 = __shfl_sync(0xffffffffu, amB, 0);
        float a3 = __shfl_sync(0xffffffffu, amB, 16);
        float mblk = fmaxf(fmaxf(a0, a1), fmaxf(a2, a3));
        if (mblk > m) {
            float sc = __expf(m - mblk);
            denom *= sc;
#pragma unroll
            for (int i = 0; i < 8; i++) accv[i] *= sc;
            m = mblk;
        }
        float e0 = __expf(a0 - m);
        float e1 = __expf(a1 - m);
        float e2 = __expf(a2 - m);
        float e3 = __expf(a3 - m);
        denom += (e0 + e1) + (e2 + e3);
        float eA = hf ? e1 : e0;
        float eB = hf ? e3 : e2;
#pragma unroll
        for (int i = 0; i < 8; i++) accv[i] += eA * fA[i] + eB * fB[i];
    }
    for (; j < cnt; j += 2) {
        bool v = (j + hf) < cnt;
        int c = v ? g_csrcol[beg + j + hf] : r;
        uint4 u = *(const uint4*)(hh + (size_t)c * HD + l16 * 8);
        float f[8];
        h16_to_f8(u, f);
        float d = f[0]*hrf[0] + f[1]*hrf[1] + f[2]*hrf[2] + f[3]*hrf[3]
                + f[4]*hrf[4] + f[5]*hrf[5] + f[6]*hrf[6] + f[7]*hrf[7];
#pragma unroll
        for (int o = 8; o; o >>= 1) d += __shfl_xor_sync(0xffffffffu, d, o);
        float am = (c == r) ? -CUDART_INF_F : ((d > 0.f) ? d : 0.2f * d);
        float a0 = __shfl_sync(0xffffffffu, am, 0);
        float a1 = __shfl_sync(0xffffffffu, am, 16);
        float mblk = fmaxf(a0, a1);
        if (mblk > m) {
            float sc = __expf(m - mblk);
            denom *= sc;
#pragma unroll
            for (int i = 0; i < 8; i++) accv[i] *= sc;
            m = mblk;
        }
        float e0 = __expf(a0 - m);
        float e1 = __expf(a1 - m);
        denom += e0 + e1;
        float em = hf ? e1 : e0;
#pragma unroll
        for (int i = 0; i < 8; i++) accv[i] += em * f[i];
    }
#pragma unroll
    for (int i = 0; i < 8; i++) accv[i] += __shfl_xor_sync(0xffffffffu, accv[i], 16);
    if (hf == 0) {
        float inv = 1.f / fmaxf(denom, 1e-16f);
        float o[8];
#pragma unroll
        for (int i = 0; i < 8; i++) o[i] = accv[i] * inv;
        *(uint4*)(g_bufOUT + (size_t)r * HD + l16 * 8) = f8_to_h16(o);
    }
}

// ---------------- final mean pool ----------------
__global__ void k_zero_out(float* out) {
    int t = threadIdx.x;
    if (t < 2 * HD) out[t] = 0.f;
}
__global__ void k_mean(float* __restrict__ out) {
    int col = threadIdx.x;                    // 128 threads
    float s = 0.f;
    for (int i = blockIdx.x; i < NND; i += gridDim.x)
        s += __half2float(g_bufOUT[(size_t)i * HD + col]);
    s *= (1.0f / NND);
    atomicAdd(&out[col], s);
    atomicAdd(&out[col + HD], s);
}

// ---------------- launch ----------------
extern "C" void kernel_launch(void* const* d_in, const int* in_sizes, int n_in,
                              void* d_out, int out_size) {
    const float* x   = (const float*)d_in[0];
    const int*   ei  = (const int*)d_in[1];     // int32 (JAX x64 disabled)
    int E = in_sizes[1] / 2;
    const int* row = ei;
    const int* col = ei + E;
    const float* Wg[3] = {(const float*)d_in[2], (const float*)d_in[6],  (const float*)d_in[10]};
    const float* bg[3] = {(const float*)d_in[3], (const float*)d_in[7],  (const float*)d_in[11]};
    const float* Wa[3] = {(const float*)d_in[4], (const float*)d_in[8],  (const float*)d_in[12]};
    const float* ba[3] = {(const float*)d_in[5], (const float*)d_in[9],  (const float*)d_in[13]};
    float* out = (float*)d_out;

    __half *pXh, *pXW, *pHH, *pACC, *pOUT;
    float *pDinv;
    cudaGetSymbolAddress((void**)&pXh,  g_Xh);
    cudaGetSymbolAddress((void**)&pXW,  g_bufXW);
    cudaGetSymbolAddress((void**)&pHH,  g_bufHH);
    cudaGetSymbolAddress((void**)&pACC, g_bufACC);
    cudaGetSymbolAddress((void**)&pOUT, g_bufOUT);
    cudaGetSymbolAddress((void**)&pDinv, g_dinv);

    const int TB = 256;
    int gN  = (NND + TB - 1) / TB;              // 157
    int gE  = (E + TB - 1) / TB;
    int gNw = NND / 8;                          // 5000 exact (warp per node)
    int gGemm = (NND + 127) / 128;              // 313
    int gXh = (NND * HD / 8 + TB - 1) / TB;     // 2500

    k_deg_init<<<gN, TB>>>();
    k_deg_count<<<gE, TB>>>(row, E);
    k_scanA<<<gN, TB>>>();                      // also computes dinv
    k_scanB<<<1, TB>>>(gN);
    k_scanC<<<gN, TB>>>();
    k_fill<<<gE, TB>>>(row, col, E);
    k_x2h<<<gXh, TB>>>(x);

    const __half* cur = pXh;
    for (int l = 0; l < 3; l++) {
        k_bperm<<<64, TB>>>(Wg[l], l > 0 ? 1 : 0);
        k_gemm_f16<<<gGemm, TB>>>(cur, nullptr, pDinv, pXW, NND);    // xwS = xw * dinv
        k_gcn<<<gNw, TB>>>(bg[l]);
        k_bperm<<<64, TB>>>(Wa[l], 0);
        k_gemm_f16<<<gGemm, TB>>>(pACC, ba[l], nullptr, pHH, NND);
        k_gat<<<gNw, TB>>>();
        cur = pOUT;
    }
    k_zero_out<<<1, TB>>>(out);
    k_mean<<<512, HD>>>(out);
}